// round 6
// baseline (speedup 1.0000x reference)
#include <cuda_runtime.h>

#define N_NODES 50000
#define N_EDGES 800000
#define D 64                  // D_IN == D_OUT == 64
#define D4 (D / 4)            // 16 float4 per row
#define CAP 64                // per-node bucket capacity (deg ~ Poisson(16))
#define RPB 64                // rows per block in fused kernel
#define WTS 68                // Wt row stride in floats (17 float4)

// Scratch (rebuilt every launch):
__device__ int g_cnt[N_NODES];            // in-degree counters / cursors
__device__ int g_edge_src[N_NODES * CAP]; // per-dst bucket of src indices

// ---------------------------------------------------------------------------
// f32x2 packed-math helpers
// ---------------------------------------------------------------------------
__device__ __forceinline__ unsigned long long pack2(float a, float b) {
    unsigned long long r;
    asm("mov.b64 %0, {%1, %2};" : "=l"(r) : "f"(a), "f"(b));
    return r;
}
__device__ __forceinline__ void unpack2(unsigned long long v, float& a, float& b) {
    asm("mov.b64 {%0, %1}, %2;" : "=f"(a), "=f"(b) : "l"(v));
}
__device__ __forceinline__ void fma2(unsigned long long& d,
                                     unsigned long long a,
                                     unsigned long long b) {
    asm("fma.rn.f32x2 %0, %1, %2, %0;" : "+l"(d) : "l"(a), "l"(b));
}
__device__ __forceinline__ float tanh_approx(float x) {
    asm("tanh.approx.f32 %0, %0;" : "+f"(x));
    return x;
}

// ---------------------------------------------------------------------------
// Kernel 1: zero the counters
// ---------------------------------------------------------------------------
__global__ void zero_cnt_kernel() {
    int i = blockIdx.x * blockDim.x + threadIdx.x;
    if (i < N_NODES) g_cnt[i] = 0;
}

// ---------------------------------------------------------------------------
// Kernel 2: bucket fill — append src to dst's bucket (int atomics, spread).
// ---------------------------------------------------------------------------
__global__ void fill_kernel(const int* __restrict__ src,
                            const int* __restrict__ dst) {
    int e = blockIdx.x * blockDim.x + threadIdx.x;
    if (e >= N_EDGES) return;
    int d = dst[e];
    int p = atomicAdd(&g_cnt[d], 1);
    if (p < CAP) g_edge_src[d * CAP + p] = src[e];
}

// ---------------------------------------------------------------------------
// Kernel 3 (fused): gather-sum -> smem -> GEMM -> tanh -> out
// 256 threads, 64 nodes per block.
// Phase A: warp gathers 8 nodes; edge indices preloaded coalesced, distributed
//          via CONVERGENT shfl (uniform trip count, predicated loads only).
// Phase B: 4x4 register-tile GEMM with float4 xs reads + fma.rn.f32x2.
// ---------------------------------------------------------------------------
__global__ __launch_bounds__(256) void gin_fused_kernel(
        const float* __restrict__ x,
        const float* __restrict__ W,
        const float* __restrict__ b,
        float* __restrict__ out) {
    __shared__ float Wt[D * WTS];     // Wt[k*WTS + j] = W[j*D + k]
    __shared__ float xs[RPB * D];     // aggregated rows

    int tid  = threadIdx.x;
    int warp = tid >> 5;
    int lane = tid & 31;
    int half = lane >> 4;
    int col  = lane & 15;
    int row0 = blockIdx.x * RPB;

    const float4* x4 = reinterpret_cast<const float4*>(x);

    // ---- load + transpose W (coalesced global reads) ----
    #pragma unroll
    for (int it = 0; it < 16; it++) {
        int i = it * 256 + tid;
        int k = i & 63;
        int j = i >> 6;
        Wt[k * WTS + j] = W[j * D + k];
    }

    // ---- Phase A: gather 8 nodes per warp into smem ----
    #pragma unroll 1
    for (int r = 0; r < 8; r++) {
        int row  = warp * 8 + r;
        int node = row0 + row;
        if (node >= N_NODES) break;          // uniform within warp

        int deg = g_cnt[node];
        if (deg > CAP) deg = CAP;
        const int* elist = g_edge_src + node * CAP;

        // coalesced preload of up to 32 edge indices
        int s_pre = (lane < deg) ? elist[lane] : 0;

        float4 a0 = make_float4(0.f, 0.f, 0.f, 0.f);
        float4 a1 = make_float4(0.f, 0.f, 0.f, 0.f);

        int dmain = deg < 32 ? deg : 32;
        int T = (dmain + 3) >> 2;            // warp-uniform trip count
        for (int t = 0; t < T; t++) {
            int i = half + 4 * t;            // <= 1 + 28 = 29; i+2 <= 31
            int s0 = __shfl_sync(0xFFFFFFFFu, s_pre, i);     // convergent
            int s1 = __shfl_sync(0xFFFFFFFFu, s_pre, i + 2); // convergent
            if (i < dmain) {
                float4 v0 = x4[s0 * D4 + col];
                a0.x += v0.x; a0.y += v0.y; a0.z += v0.z; a0.w += v0.w;
            }
            if (i + 2 < dmain) {
                float4 v1 = x4[s1 * D4 + col];
                a1.x += v1.x; a1.y += v1.y; a1.z += v1.z; a1.w += v1.w;
            }
        }
        for (int j = 32 + half; j < deg; j += 2) {   // rare: deg > 32 (no shfl)
            int s = elist[j];
            float4 v = x4[s * D4 + col];
            a0.x += v.x; a0.y += v.y; a0.z += v.z; a0.w += v.w;
        }

        a0.x += a1.x; a0.y += a1.y; a0.z += a1.z; a0.w += a1.w;

        // combine halves (all lanes execute — convergent)
        a0.x += __shfl_xor_sync(0xFFFFFFFFu, a0.x, 16);
        a0.y += __shfl_xor_sync(0xFFFFFFFFu, a0.y, 16);
        a0.z += __shfl_xor_sync(0xFFFFFFFFu, a0.z, 16);
        a0.w += __shfl_xor_sync(0xFFFFFFFFu, a0.w, 16);

        if (half == 0) {
            float4 sv = x4[node * D4 + col];   // self term ((1+eps)*x, eps=0)
            a0.x += sv.x; a0.y += sv.y; a0.z += sv.z; a0.w += sv.w;
            reinterpret_cast<float4*>(xs)[row * D4 + col] = a0;
        }
    }
    __syncthreads();

    // ---- Phase B: out = tanh(xs @ W^T + b) ----
    int rq = tid >> 4;                   // 0..15
    int cg = tid & 15;                   // col group (4 cols)
    int r0 = rq * 4;

    float4 bb = reinterpret_cast<const float4*>(b)[cg];
    unsigned long long a01[4], a23[4];
    #pragma unroll
    for (int rr = 0; rr < 4; rr++) {
        a01[rr] = pack2(bb.x, bb.y);
        a23[rr] = pack2(bb.z, bb.w);
    }

    const float4* xs4 = reinterpret_cast<const float4*>(xs);
    const float4* Wt4 = reinterpret_cast<const float4*>(Wt);

    #pragma unroll 8
    for (int g = 0; g < 16; g++) {
        float4 xv[4];
        #pragma unroll
        for (int rr = 0; rr < 4; rr++)
            xv[rr] = xs4[(r0 + rr) * 16 + g];
        #pragma unroll
        for (int kk = 0; kk < 4; kk++) {
            float4 w = Wt4[(g * 4 + kk) * (WTS / 4) + cg];
            unsigned long long w01 = pack2(w.x, w.y);
            unsigned long long w23 = pack2(w.z, w.w);
            #pragma unroll
            for (int rr = 0; rr < 4; rr++) {
                float xk = (kk == 0) ? xv[rr].x :
                           (kk == 1) ? xv[rr].y :
                           (kk == 2) ? xv[rr].z : xv[rr].w;
                unsigned long long x2 = pack2(xk, xk);
                fma2(a01[rr], x2, w01);
                fma2(a23[rr], x2, w23);
            }
        }
    }

    #pragma unroll
    for (int rr = 0; rr < 4; rr++) {
        int row = row0 + r0 + rr;
        if (row < N_NODES) {
            float4 o;
            unpack2(a01[rr], o.x, o.y);
            unpack2(a23[rr], o.z, o.w);
            o.x = tanh_approx(o.x);
            o.y = tanh_approx(o.y);
            o.z = tanh_approx(o.z);
            o.w = tanh_approx(o.w);
            reinterpret_cast<float4*>(out)[row * D4 + cg] = o;
        }
    }
}

// ---------------------------------------------------------------------------
// Launch
// ---------------------------------------------------------------------------
extern "C" void kernel_launch(void* const* d_in, const int* in_sizes, int n_in,
                              void* d_out, int out_size) {
    const float* x   = (const float*)d_in[0];       // [N, 64]
    const float* W   = (const float*)d_in[1];       // [64, 64]
    const float* b   = (const float*)d_in[2];       // [64]
    const int*   src = (const int*)d_in[3];         // [E] int32
    const int*   dst = (const int*)d_in[4];         // [E] int32
    float*       out = (float*)d_out;               // [N, 64]

    zero_cnt_kernel<<<(N_NODES + 255) / 256, 256>>>();
    fill_kernel<<<(N_EDGES + 255) / 256, 256>>>(src, dst);
    gin_fused_kernel<<<(N_NODES + RPB - 1) / RPB, 256>>>(x, W, b, out);
}

// round 7
// speedup vs baseline: 1.0587x; 1.0587x over previous
#include <cuda_runtime.h>

#define N_NODES 50000
#define N_EDGES 800000
#define D 64                  // D_IN == D_OUT == 64
#define D4 (D / 4)            // 16 float4 per row
#define CAP 64                // per-node bucket capacity (deg ~ Poisson(16))
#define RPB 64                // rows per block in gemm
#define WTS 68                // Wt row stride (floats) = 17 float4
#define XCS 68                // xs_c column stride (floats)

// Scratch (g_cnt zeroed at end of gather -> ready for next replay):
__device__ int   g_cnt[N_NODES];
__device__ int   g_edge_src[N_NODES * CAP];
__device__ float g_agg[N_NODES * D];

// ---------------------------------------------------------------------------
// f32x2 packed-math helpers
// ---------------------------------------------------------------------------
__device__ __forceinline__ unsigned long long pack2(float a, float b) {
    unsigned long long r;
    asm("mov.b64 %0, {%1, %2};" : "=l"(r) : "f"(a), "f"(b));
    return r;
}
__device__ __forceinline__ void unpack2(unsigned long long v, float& a, float& b) {
    asm("mov.b64 {%0, %1}, %2;" : "=f"(a), "=f"(b) : "l"(v));
}
__device__ __forceinline__ void fma2(unsigned long long& d,
                                     unsigned long long a,
                                     unsigned long long b) {
    asm("fma.rn.f32x2 %0, %1, %2, %0;" : "+l"(d) : "l"(a), "l"(b));
}
__device__ __forceinline__ float tanh_approx(float x) {
    asm("tanh.approx.f32 %0, %0;" : "+f"(x));
    return x;
}

// ---------------------------------------------------------------------------
// Kernel 1: bucket fill — 4 edges per thread, int4 index reads.
// ---------------------------------------------------------------------------
__global__ void fill_kernel(const int* __restrict__ src,
                            const int* __restrict__ dst) {
    int e4 = blockIdx.x * blockDim.x + threadIdx.x;
    if (e4 >= N_EDGES / 4) return;
    int4 s = reinterpret_cast<const int4*>(src)[e4];
    int4 d = reinterpret_cast<const int4*>(dst)[e4];
    int p;
    p = atomicAdd(&g_cnt[d.x], 1); if (p < CAP) g_edge_src[d.x * CAP + p] = s.x;
    p = atomicAdd(&g_cnt[d.y], 1); if (p < CAP) g_edge_src[d.y * CAP + p] = s.y;
    p = atomicAdd(&g_cnt[d.z], 1); if (p < CAP) g_edge_src[d.z * CAP + p] = s.z;
    p = atomicAdd(&g_cnt[d.w], 1); if (p < CAP) g_edge_src[d.w * CAP + p] = s.w;
}

// ---------------------------------------------------------------------------
// Kernel 2: gather-sum + self term. One warp per node.
// Edge indices preloaded coalesced, distributed by CONVERGENT shfl
// (uniform trip count; only loads predicated). Zeroes g_cnt afterwards.
// ---------------------------------------------------------------------------
__global__ void gather_kernel(const float* __restrict__ x) {
    int node = (blockIdx.x * blockDim.x + threadIdx.x) >> 5;
    if (node >= N_NODES) return;
    int lane = threadIdx.x & 31;
    int half = lane >> 4;        // 0 or 1
    int col  = lane & 15;        // float4 column

    int deg = g_cnt[node];
    if (deg > CAP) deg = CAP;
    const int* elist = g_edge_src + node * CAP;
    const float4* x4 = reinterpret_cast<const float4*>(x);

    int s_pre = (lane < deg) ? elist[lane] : 0;   // coalesced preload

    float4 a0 = make_float4(0.f, 0.f, 0.f, 0.f);
    float4 a1 = make_float4(0.f, 0.f, 0.f, 0.f);

    int dmain = deg < 32 ? deg : 32;
    int T = (dmain + 3) >> 2;                     // warp-uniform
    for (int t = 0; t < T; t++) {
        int i = half + 4 * t;                     // max 29; i+2 max 31
        int s0 = __shfl_sync(0xFFFFFFFFu, s_pre, i);
        int s1 = __shfl_sync(0xFFFFFFFFu, s_pre, i + 2);
        if (i < dmain) {
            float4 v = x4[s0 * D4 + col];
            a0.x += v.x; a0.y += v.y; a0.z += v.z; a0.w += v.w;
        }
        if (i + 2 < dmain) {
            float4 v = x4[s1 * D4 + col];
            a1.x += v.x; a1.y += v.y; a1.z += v.z; a1.w += v.w;
        }
    }
    for (int j = 32 + half; j < deg; j += 2) {    // rare: deg > 32
        int s = elist[j];
        float4 v = x4[s * D4 + col];
        a0.x += v.x; a0.y += v.y; a0.z += v.z; a0.w += v.w;
    }

    a0.x += a1.x; a0.y += a1.y; a0.z += a1.z; a0.w += a1.w;

    a0.x += __shfl_xor_sync(0xFFFFFFFFu, a0.x, 16);
    a0.y += __shfl_xor_sync(0xFFFFFFFFu, a0.y, 16);
    a0.z += __shfl_xor_sync(0xFFFFFFFFu, a0.z, 16);
    a0.w += __shfl_xor_sync(0xFFFFFFFFu, a0.w, 16);

    if (half == 0) {
        float4 sv = x4[node * D4 + col];          // self term (eps = 0)
        a0.x += sv.x; a0.y += sv.y; a0.z += sv.z; a0.w += sv.w;
        reinterpret_cast<float4*>(g_agg)[node * D4 + col] = a0;
    } else if (lane == 16) {
        g_cnt[node] = 0;                          // reset for next replay
    }
}

// ---------------------------------------------------------------------------
// Kernel 3: out = tanh(agg @ W^T + b)
// 64 rows/block, 256 threads, 4x4 register tile, fma.rn.f32x2.
// xs stored COLUMN-major (xs_c[k*68 + row]) -> mainloop reads a float4 of
// 4 rows per column: 2-way bank conflict instead of 16-way.
// ---------------------------------------------------------------------------
__global__ __launch_bounds__(256) void gemm_tanh_kernel(
        const float* __restrict__ W,
        const float* __restrict__ b,
        float* __restrict__ out) {
    __shared__ float Wt[D * WTS];        // Wt[k*WTS + j] = W[j*D + k]
    __shared__ float xs_c[D * XCS];      // xs_c[k*XCS + row]

    int tid  = threadIdx.x;
    int row0 = blockIdx.x * RPB;

    // load + transpose W (coalesced reads)
    #pragma unroll
    for (int it = 0; it < 16; it++) {
        int i = it * 256 + tid;
        int k = i & 63;
        int j = i >> 6;
        Wt[k * WTS + j] = W[j * D + k];
    }

    // load 64 agg rows, store transposed into xs_c
    #pragma unroll
    for (int it = 0; it < 4; it++) {
        int idx = it * 256 + tid;        // float4 tile index
        int r = idx >> 4;                // row 0..63
        int c = idx & 15;                // float4 col group
        float4 v = make_float4(0.f, 0.f, 0.f, 0.f);
        if (row0 + r < N_NODES)
            v = reinterpret_cast<const float4*>(g_agg)[(row0 + r) * D4 + c];
        xs_c[(4 * c + 0) * XCS + r] = v.x;
        xs_c[(4 * c + 1) * XCS + r] = v.y;
        xs_c[(4 * c + 2) * XCS + r] = v.z;
        xs_c[(4 * c + 3) * XCS + r] = v.w;
    }
    __syncthreads();

    int rq = tid >> 4;                   // row quad 0..15
    int cg = tid & 15;                   // col group
    int r0 = rq * 4;

    float4 bb = reinterpret_cast<const float4*>(b)[cg];
    unsigned long long a01[4], a23[4];
    #pragma unroll
    for (int rr = 0; rr < 4; rr++) {
        a01[rr] = pack2(bb.x, bb.y);
        a23[rr] = pack2(bb.z, bb.w);
    }

    const float4* Wt4 = reinterpret_cast<const float4*>(Wt);

    #pragma unroll 8
    for (int k = 0; k < D; k++) {
        float4 xv = *reinterpret_cast<const float4*>(&xs_c[k * XCS + r0]);
        float4 w  = Wt4[k * (WTS / 4) + cg];
        unsigned long long w01 = pack2(w.x, w.y);
        unsigned long long w23 = pack2(w.z, w.w);
        unsigned long long x0 = pack2(xv.x, xv.x);
        unsigned long long x1 = pack2(xv.y, xv.y);
        unsigned long long x2 = pack2(xv.z, xv.z);
        unsigned long long x3 = pack2(xv.w, xv.w);
        fma2(a01[0], x0, w01); fma2(a23[0], x0, w23);
        fma2(a01[1], x1, w01); fma2(a23[1], x1, w23);
        fma2(a01[2], x2, w01); fma2(a23[2], x2, w23);
        fma2(a01[3], x3, w01); fma2(a23[3], x3, w23);
    }

    #pragma unroll
    for (int rr = 0; rr < 4; rr++) {
        int row = row0 + r0 + rr;
        if (row < N_NODES) {
            float4 o;
            unpack2(a01[rr], o.x, o.y);
            unpack2(a23[rr], o.z, o.w);
            o.x = tanh_approx(o.x);
            o.y = tanh_approx(o.y);
            o.z = tanh_approx(o.z);
            o.w = tanh_approx(o.w);
            reinterpret_cast<float4*>(out)[row * D4 + cg] = o;
        }
    }
}

// ---------------------------------------------------------------------------
// Launch  (g_cnt starts zero: BSS init on call #1, gather re-zeroes after)
// ---------------------------------------------------------------------------
extern "C" void kernel_launch(void* const* d_in, const int* in_sizes, int n_in,
                              void* d_out, int out_size) {
    const float* x   = (const float*)d_in[0];       // [N, 64]
    const float* W   = (const float*)d_in[1];       // [64, 64]
    const float* b   = (const float*)d_in[2];       // [64]
    const int*   src = (const int*)d_in[3];         // [E] int32
    const int*   dst = (const int*)d_in[4];         // [E] int32
    float*       out = (float*)d_out;               // [N, 64]

    fill_kernel<<<(N_EDGES / 4 + 255) / 256, 256>>>(src, dst);
    {
        int warps_per_block = 8;
        int blocks = (N_NODES + warps_per_block - 1) / warps_per_block;
        gather_kernel<<<blocks, 256>>>(x);
    }
    gemm_tanh_kernel<<<(N_NODES + RPB - 1) / RPB, 256>>>(W, b, out);
}

// round 8
// speedup vs baseline: 1.0712x; 1.0118x over previous
#include <cuda_runtime.h>

#define N_NODES 50000
#define N_EDGES 800000
#define D 64                  // D_IN == D_OUT == 64
#define D4 (D / 4)            // 16 float4 per row
#define CAP 64                // per-node bucket capacity (deg ~ Poisson(16))
#define RPB 64                // rows per block in gemm
#define WTS 68                // Wt row stride (floats) = 17 float4
#define XCS 68                // xs_c column stride (floats)

// Scratch (g_cnt zeroed at end of gather -> ready for next replay):
__device__ int   g_cnt[N_NODES];
__device__ int   g_edge_src[N_NODES * CAP];
__device__ float g_agg[N_NODES * D];

// ---------------------------------------------------------------------------
// f32x2 packed-math helpers
// ---------------------------------------------------------------------------
__device__ __forceinline__ unsigned long long pack2(float a, float b) {
    unsigned long long r;
    asm("mov.b64 %0, {%1, %2};" : "=l"(r) : "f"(a), "f"(b));
    return r;
}
__device__ __forceinline__ void unpack2(unsigned long long v, float& a, float& b) {
    asm("mov.b64 {%0, %1}, %2;" : "=f"(a), "=f"(b) : "l"(v));
}
__device__ __forceinline__ void fma2(unsigned long long& d,
                                     unsigned long long a,
                                     unsigned long long b) {
    asm("fma.rn.f32x2 %0, %1, %2, %0;" : "+l"(d) : "l"(a), "l"(b));
}
__device__ __forceinline__ float tanh_approx(float x) {
    asm("tanh.approx.f32 %0, %0;" : "+f"(x));
    return x;
}

// ---------------------------------------------------------------------------
// Kernel 1: bucket fill — ONE edge per thread (max MLP to hide ATOMG latency)
// ---------------------------------------------------------------------------
__global__ void fill_kernel(const int* __restrict__ src,
                            const int* __restrict__ dst) {
    int e = blockIdx.x * blockDim.x + threadIdx.x;
    if (e >= N_EDGES) return;
    int d = dst[e];
    int s = src[e];
    int p = atomicAdd(&g_cnt[d], 1);
    if (p < CAP) g_edge_src[d * CAP + p] = s;
}

// ---------------------------------------------------------------------------
// Kernel 2: gather-sum + self term. One warp per node.
// Edge indices preloaded coalesced, distributed by CONVERGENT shfl
// (uniform trip count; only loads predicated). Zeroes g_cnt afterwards.
// ---------------------------------------------------------------------------
__global__ void gather_kernel(const float* __restrict__ x) {
    int node = (blockIdx.x * blockDim.x + threadIdx.x) >> 5;
    if (node >= N_NODES) return;
    int lane = threadIdx.x & 31;
    int half = lane >> 4;        // 0 or 1
    int col  = lane & 15;        // float4 column

    int deg = g_cnt[node];
    if (deg > CAP) deg = CAP;
    const int* elist = g_edge_src + node * CAP;
    const float4* x4 = reinterpret_cast<const float4*>(x);

    int s_pre = (lane < deg) ? elist[lane] : 0;   // coalesced preload

    float4 a0 = make_float4(0.f, 0.f, 0.f, 0.f);
    float4 a1 = make_float4(0.f, 0.f, 0.f, 0.f);

    int dmain = deg < 32 ? deg : 32;
    int T = (dmain + 3) >> 2;                     // warp-uniform
    for (int t = 0; t < T; t++) {
        int i = half + 4 * t;                     // max 29; i+2 max 31
        int s0 = __shfl_sync(0xFFFFFFFFu, s_pre, i);
        int s1 = __shfl_sync(0xFFFFFFFFu, s_pre, i + 2);
        if (i < dmain) {
            float4 v = x4[s0 * D4 + col];
            a0.x += v.x; a0.y += v.y; a0.z += v.z; a0.w += v.w;
        }
        if (i + 2 < dmain) {
            float4 v = x4[s1 * D4 + col];
            a1.x += v.x; a1.y += v.y; a1.z += v.z; a1.w += v.w;
        }
    }
    for (int j = 32 + half; j < deg; j += 2) {    // rare: deg > 32
        int s = elist[j];
        float4 v = x4[s * D4 + col];
        a0.x += v.x; a0.y += v.y; a0.z += v.z; a0.w += v.w;
    }

    a0.x += a1.x; a0.y += a1.y; a0.z += a1.z; a0.w += a1.w;

    a0.x += __shfl_xor_sync(0xFFFFFFFFu, a0.x, 16);
    a0.y += __shfl_xor_sync(0xFFFFFFFFu, a0.y, 16);
    a0.z += __shfl_xor_sync(0xFFFFFFFFu, a0.z, 16);
    a0.w += __shfl_xor_sync(0xFFFFFFFFu, a0.w, 16);

    if (half == 0) {
        float4 sv = x4[node * D4 + col];          // self term (eps = 0)
        a0.x += sv.x; a0.y += sv.y; a0.z += sv.z; a0.w += sv.w;
        reinterpret_cast<float4*>(g_agg)[node * D4 + col] = a0;
    } else if (lane == 16) {
        g_cnt[node] = 0;                          // reset for next replay
    }
}

// ---------------------------------------------------------------------------
// Kernel 3: out = tanh(agg @ W^T + b)
// 64 rows/block, 256 threads, 4x4 register tile, fma.rn.f32x2.
// xs stored COLUMN-major (xs_c[k*68 + row]).
// ---------------------------------------------------------------------------
__global__ __launch_bounds__(256) void gemm_tanh_kernel(
        const float* __restrict__ W,
        const float* __restrict__ b,
        float* __restrict__ out) {
    __shared__ float Wt[D * WTS];        // Wt[k*WTS + j] = W[j*D + k]
    __shared__ float xs_c[D * XCS];      // xs_c[k*XCS + row]

    int tid  = threadIdx.x;
    int row0 = blockIdx.x * RPB;

    // load + transpose W (coalesced reads)
    #pragma unroll
    for (int it = 0; it < 16; it++) {
        int i = it * 256 + tid;
        int k = i & 63;
        int j = i >> 6;
        Wt[k * WTS + j] = W[j * D + k];
    }

    // load 64 agg rows, store transposed into xs_c
    #pragma unroll
    for (int it = 0; it < 4; it++) {
        int idx = it * 256 + tid;        // float4 tile index
        int r = idx >> 4;                // row 0..63
        int c = idx & 15;                // float4 col group
        float4 v = make_float4(0.f, 0.f, 0.f, 0.f);
        if (row0 + r < N_NODES)
            v = reinterpret_cast<const float4*>(g_agg)[(row0 + r) * D4 + c];
        xs_c[(4 * c + 0) * XCS + r] = v.x;
        xs_c[(4 * c + 1) * XCS + r] = v.y;
        xs_c[(4 * c + 2) * XCS + r] = v.z;
        xs_c[(4 * c + 3) * XCS + r] = v.w;
    }
    __syncthreads();

    int rq = tid >> 4;                   // row quad 0..15
    int cg = tid & 15;                   // col group
    int r0 = rq * 4;

    float4 bb = reinterpret_cast<const float4*>(b)[cg];
    unsigned long long a01[4], a23[4];
    #pragma unroll
    for (int rr = 0; rr < 4; rr++) {
        a01[rr] = pack2(bb.x, bb.y);
        a23[rr] = pack2(bb.z, bb.w);
    }

    const float4* Wt4 = reinterpret_cast<const float4*>(Wt);

    #pragma unroll 8
    for (int k = 0; k < D; k++) {
        float4 xv = *reinterpret_cast<const float4*>(&xs_c[k * XCS + r0]);
        float4 w  = Wt4[k * (WTS / 4) + cg];
        unsigned long long w01 = pack2(w.x, w.y);
        unsigned long long w23 = pack2(w.z, w.w);
        unsigned long long x0 = pack2(xv.x, xv.x);
        unsigned long long x1 = pack2(xv.y, xv.y);
        unsigned long long x2 = pack2(xv.z, xv.z);
        unsigned long long x3 = pack2(xv.w, xv.w);
        fma2(a01[0], x0, w01); fma2(a23[0], x0, w23);
        fma2(a01[1], x1, w01); fma2(a23[1], x1, w23);
        fma2(a01[2], x2, w01); fma2(a23[2], x2, w23);
        fma2(a01[3], x3, w01); fma2(a23[3], x3, w23);
    }

    #pragma unroll
    for (int rr = 0; rr < 4; rr++) {
        int row = row0 + r0 + rr;
        if (row < N_NODES) {
            float4 o;
            unpack2(a01[rr], o.x, o.y);
            unpack2(a23[rr], o.z, o.w);
            o.x = tanh_approx(o.x);
            o.y = tanh_approx(o.y);
            o.z = tanh_approx(o.z);
            o.w = tanh_approx(o.w);
            reinterpret_cast<float4*>(out)[row * D4 + cg] = o;
        }
    }
}

// ---------------------------------------------------------------------------
// Launch  (g_cnt starts zero: BSS init on call #1, gather re-zeroes after)
// ---------------------------------------------------------------------------
extern "C" void kernel_launch(void* const* d_in, const int* in_sizes, int n_in,
                              void* d_out, int out_size) {
    const float* x   = (const float*)d_in[0];       // [N, 64]
    const float* W   = (const float*)d_in[1];       // [64, 64]
    const float* b   = (const float*)d_in[2];       // [64]
    const int*   src = (const int*)d_in[3];         // [E] int32
    const int*   dst = (const int*)d_in[4];         // [E] int32
    float*       out = (float*)d_out;               // [N, 64]

    fill_kernel<<<(N_EDGES + 255) / 256, 256>>>(src, dst);
    {
        int warps_per_block = 8;
        int blocks = (N_NODES + warps_per_block - 1) / warps_per_block;
        gather_kernel<<<blocks, 256>>>(x);
    }
    gemm_tanh_kernel<<<(N_NODES + RPB - 1) / RPB, 256>>>(W, b, out);
}